// round 1
// baseline (speedup 1.0000x reference)
#include <cuda_runtime.h>
#include <cstdint>

#define S_LEN 2048
#define D_DIM 128
#define TK    32
#define QPB   128
#define KTOP  32

typedef unsigned long long u64;

// Packed dual-fp32 FMA (sm_103a FFMA2). Accumulates (lo,hi) partial dot products.
__device__ __forceinline__ u64 ffma2(u64 a, u64 b, u64 c) {
    u64 d;
    asm("fma.rn.f32x2 %0, %1, %2, %3;" : "=l"(d) : "l"(a), "l"(b), "l"(c));
    return d;
}

__global__ __launch_bounds__(QPB, 3)
void topk_attn_kernel(const float* __restrict__ Qg, const float* __restrict__ Kg,
                      const float* __restrict__ Vg, float* __restrict__ Og) {
    extern __shared__ float smem[];
    float* Kt   = smem;                               // TK*D_DIM floats (16KB)
    float* topv = smem + TK * D_DIM;                  // QPB*(KTOP+1), padded rows
    int*   topi = (int*)(topv + QPB * (KTOP + 1));
    float* sbuf = (float*)(topi + QPB * (KTOP + 1));

    const int tid = threadIdx.x;
    const int bh  = blockIdx.y;
    const int q0  = blockIdx.x * QPB;

    const float* Qrow = Qg + ((size_t)bh * S_LEN + q0 + tid) * D_DIM;
    const float* Kb   = Kg + (size_t)bh * S_LEN * D_DIM;
    const float* Vb   = Vg + (size_t)bh * S_LEN * D_DIM;

    float* mytopv = topv + tid * (KTOP + 1);
    int*   mytopi = topi + tid * (KTOP + 1);
    float* mysbuf = sbuf + tid * (KTOP + 1);

    #pragma unroll
    for (int i = 0; i < KTOP; i++) mytopv[i] = -3.402823466e38f;
    float minv   = -3.402823466e38f;
    int   minpos = 0;

    for (int kt = 0; kt < S_LEN; kt += TK) {
        __syncthreads();
        // Cooperative K-tile load: 32 keys x 128 dims = 16KB contiguous, coalesced.
        const float4* src = (const float4*)(Kb + (size_t)kt * D_DIM);
        float4* dst = (float4*)Kt;
        #pragma unroll
        for (int i = 0; i < 8; i++) dst[tid + i * QPB] = __ldg(src + tid + i * QPB);
        __syncthreads();

        u64 acc[TK];
        #pragma unroll
        for (int j = 0; j < TK; j++) acc[j] = 0ull;

        // Scores: thread owns one query; f32x2 packs adjacent dims.
        #pragma unroll 1
        for (int c = 0; c < 4; c++) {
            ulonglong2 qq[8];
            const ulonglong2* qsrc = (const ulonglong2*)(Qrow + c * 32);
            #pragma unroll
            for (int i = 0; i < 8; i++) qq[i] = __ldg(qsrc + i);
            #pragma unroll
            for (int j = 0; j < TK; j++) {
                const ulonglong2* krow = (const ulonglong2*)(Kt + j * D_DIM + c * 32);
                #pragma unroll
                for (int i = 0; i < 8; i++) {
                    ulonglong2 kv = krow[i];          // ld.shared.v2.u64 (broadcast)
                    acc[j] = ffma2(kv.x, qq[i].x, acc[j]);
                    acc[j] = ffma2(kv.y, qq[i].y, acc[j]);
                }
            }
        }

        // Finalize: s = lo + hi of each packed accumulator.
        #pragma unroll
        for (int j = 0; j < TK; j++) {
            union { u64 u; float2 f; } s; s.u = acc[j];
            mysbuf[j] = s.f.x + s.f.y;
        }

        // Streaming top-32: replace current min, rescan (rare after warmup).
        #pragma unroll 1
        for (int j = 0; j < TK; j++) {
            float s = mysbuf[j];
            if (s > minv) {
                mytopv[minpos] = s;
                mytopi[minpos] = kt + j;
                minv = mytopv[0]; minpos = 0;
                #pragma unroll 1
                for (int i = 1; i < KTOP; i++) {
                    float v = mytopv[i];
                    if (v < minv) { minv = v; minpos = i; }
                }
            }
        }
    }

    // Softmax over the selected 32 (per-thread).
    float m = -3.402823466e38f;
    #pragma unroll 1
    for (int i = 0; i < KTOP; i++) m = fmaxf(m, mytopv[i]);
    float ssum = 0.f;
    #pragma unroll 1
    for (int i = 0; i < KTOP; i++) { float e = __expf(mytopv[i] - m); ssum += e; mytopv[i] = e; }
    float inv = 1.0f / ssum;
    #pragma unroll 1
    for (int i = 0; i < KTOP; i++) mytopv[i] *= inv;
    __syncthreads();

    // Warp-cooperative epilogue: each V row read exactly once, fully coalesced
    // (lane l covers dims [4l, 4l+4)); output rows coalesced too.
    const int lane  = tid & 31;
    const int wbase = tid & ~31;
    float* Ob = Og + ((size_t)bh * S_LEN + q0) * D_DIM;
    #pragma unroll 1
    for (int qi = 0; qi < 32; qi++) {
        const int tq = wbase + qi;
        const float* tv = topv + tq * (KTOP + 1);
        const int*   ti = topi + tq * (KTOP + 1);
        float4 a = make_float4(0.f, 0.f, 0.f, 0.f);
        #pragma unroll 4
        for (int j = 0; j < KTOP; j++) {
            float p  = tv[j];
            int  idx = ti[j];
            float4 v = __ldg((const float4*)(Vb + (size_t)idx * D_DIM) + lane);
            a.x += p * v.x; a.y += p * v.y; a.z += p * v.z; a.w += p * v.w;
        }
        ((float4*)(Ob + (size_t)tq * D_DIM))[lane] = a;
    }
}

extern "C" void kernel_launch(void* const* d_in, const int* in_sizes, int n_in,
                              void* d_out, int out_size) {
    const float* Q = (const float*)d_in[0];
    const float* K = (const float*)d_in[1];
    const float* V = (const float*)d_in[2];
    float* O = (float*)d_out;
    const int BH = in_sizes[0] / (S_LEN * D_DIM);   // 32 for the bench shapes
    const size_t smem_bytes = (TK * D_DIM + 3 * QPB * (KTOP + 1)) * sizeof(float); // 67072
    cudaFuncSetAttribute(topk_attn_kernel,
                         cudaFuncAttributeMaxDynamicSharedMemorySize, (int)smem_bytes);
    dim3 grid(S_LEN / QPB, BH);
    topk_attn_kernel<<<grid, QPB, smem_bytes>>>(Q, K, V, O);
}

// round 3
// speedup vs baseline: 1.1331x; 1.1331x over previous
#include <cuda_runtime.h>
#include <cuda_bf16.h>
#include <cstdint>

#define S_LEN 2048
#define D_DIM 128
#define QPB   128          // queries per CTA
#define NTILE 128          // keys per iteration
#define KTOP  32
#define NKT   (S_LEN / NTILE)
#define NTHREADS 256       // 8 warps, warp w owns query rows [16w,16w+16)

// smem row stride for bf16 tiles: 272B = 17*16B -> conflict-free ldmatrix
#define RSTRIDE 272
// score row stride in floats: 129 -> conflict-free selection reads
#define SSTRIDE 129

#define OFF_KHI  0
#define OFF_KLO  (OFF_KHI + 128 * RSTRIDE)                 // 34816
#define OFF_SC   (OFF_KLO + 128 * RSTRIDE)                 // 69632
#define OFF_TOPV (OFF_SC + 128 * SSTRIDE * 4)              // +66048 = 135680
#define OFF_TOPI (OFF_TOPV + QPB * 33 * 4)                 // +16896
#define SMEM_TOTAL (OFF_TOPI + QPB * 33 * 4)               // 169472

__device__ __forceinline__ uint32_t smem_u32(const void* p) {
    uint32_t a;
    asm("{ .reg .u64 t; cvta.to.shared.u64 t, %1; cvt.u32.u64 %0, t; }" : "=r"(a) : "l"(p));
    return a;
}

__device__ __forceinline__ void ldsm4(uint32_t& r0, uint32_t& r1, uint32_t& r2, uint32_t& r3,
                                      uint32_t addr) {
    asm volatile("ldmatrix.sync.aligned.m8n8.x4.shared.b16 {%0,%1,%2,%3}, [%4];"
                 : "=r"(r0), "=r"(r1), "=r"(r2), "=r"(r3) : "r"(addr));
}

__device__ __forceinline__ void mma16816(float* c, const uint32_t* a, uint32_t b0, uint32_t b1) {
    asm volatile(
        "mma.sync.aligned.m16n8k16.row.col.f32.bf16.bf16.f32 "
        "{%0,%1,%2,%3}, {%4,%5,%6,%7}, {%8,%9}, {%0,%1,%2,%3};"
        : "+f"(c[0]), "+f"(c[1]), "+f"(c[2]), "+f"(c[3])
        : "r"(a[0]), "r"(a[1]), "r"(a[2]), "r"(a[3]), "r"(b0), "r"(b1));
}

// Split one 128x128 fp32 tile (row-major, 128-float rows) into bf16 hi/lo smem
// tiles with RSTRIDE rows. Warp per row, 16 passes, LDG.128 coalesced.
__device__ __forceinline__ void split_tile(char* smem, uint32_t hi_off, uint32_t lo_off,
                                           const float4* __restrict__ gsrc,
                                           int wid, int lane) {
    #pragma unroll
    for (int pass = 0; pass < 16; pass++) {
        const int row = pass * 8 + wid;
        float4 v = __ldg(gsrc + (size_t)row * 32 + lane);
        __nv_bfloat16 h0 = __float2bfloat16(v.x), h1 = __float2bfloat16(v.y);
        __nv_bfloat16 h2 = __float2bfloat16(v.z), h3 = __float2bfloat16(v.w);
        __nv_bfloat16 l0 = __float2bfloat16(v.x - __bfloat162float(h0));
        __nv_bfloat16 l1 = __float2bfloat16(v.y - __bfloat162float(h1));
        __nv_bfloat16 l2 = __float2bfloat16(v.z - __bfloat162float(h2));
        __nv_bfloat16 l3 = __float2bfloat16(v.w - __bfloat162float(h3));
        uint2 hp, lp;
        hp.x = (uint32_t)__bfloat16_as_ushort(h0) | ((uint32_t)__bfloat16_as_ushort(h1) << 16);
        hp.y = (uint32_t)__bfloat16_as_ushort(h2) | ((uint32_t)__bfloat16_as_ushort(h3) << 16);
        lp.x = (uint32_t)__bfloat16_as_ushort(l0) | ((uint32_t)__bfloat16_as_ushort(l1) << 16);
        lp.y = (uint32_t)__bfloat16_as_ushort(l2) | ((uint32_t)__bfloat16_as_ushort(l3) << 16);
        *(uint2*)(smem + hi_off + row * RSTRIDE + lane * 8) = hp;
        *(uint2*)(smem + lo_off + row * RSTRIDE + lane * 8) = lp;
    }
}

__global__ __launch_bounds__(NTHREADS, 1)
void topk_attn_hmma(const float* __restrict__ Qg, const float* __restrict__ Kg,
                    const float* __restrict__ Vg, float* __restrict__ Og) {
    extern __shared__ char smem[];
    const int tid  = threadIdx.x;
    const int wid  = tid >> 5;
    const int lane = tid & 31;
    const int bh   = blockIdx.y;
    const int q0   = blockIdx.x * QPB;

    const float* Kb = Kg + (size_t)bh * S_LEN * D_DIM;
    const float* Vb = Vg + (size_t)bh * S_LEN * D_DIM;

    // ---- Stage Q (reusing K buffers), load A-fragments into registers ----
    split_tile(smem, OFF_KHI, OFF_KLO,
               (const float4*)(Qg + ((size_t)bh * S_LEN + q0) * D_DIM), wid, lane);
    __syncthreads();

    // A-frag ldmatrix address: rows [16w + ((l>>3)&1)*8 + (l&7)], k half = (l>>4)*8
    const uint32_t a_off = (uint32_t)((16 * wid + (((lane >> 3) & 1) << 3) + (lane & 7)) * RSTRIDE
                                      + ((lane >> 4) << 4));
    const uint32_t sb = smem_u32(smem);
    uint32_t qhi[8][4], qlo[8][4];
    #pragma unroll
    for (int ks = 0; ks < 8; ks++) {
        ldsm4(qhi[ks][0], qhi[ks][1], qhi[ks][2], qhi[ks][3], sb + OFF_KHI + a_off + ks * 32);
        ldsm4(qlo[ks][0], qlo[ks][1], qlo[ks][2], qlo[ks][3], sb + OFF_KLO + a_off + ks * 32);
    }
    __syncthreads();

    // ---- top-k state (thread q<128 owns query q0+q) ----
    float* mytopv = (float*)(smem + OFF_TOPV) + tid * 33;
    int*   mytopi = (int*)(smem + OFF_TOPI) + tid * 33;
    float minv = -3.402823466e38f;
    int   minpos = 0;
    if (tid < QPB) {
        #pragma unroll
        for (int i = 0; i < KTOP; i++) mytopv[i] = -3.402823466e38f;
    }

    // B-frag ldmatrix address: rows [n0 + ((l>>4)&1)*8 + (l&7)], k half = ((l>>3)&1)*8
    const uint32_t b_off = (uint32_t)(((((lane >> 4) & 1) << 3) + (lane & 7)) * RSTRIDE
                                      + (((lane >> 3) & 1) << 4));
    float* scores = (float*)(smem + OFF_SC);

    for (int kt = 0; kt < NKT; kt++) {
        __syncthreads();  // prior ldmatrix reads + selection reads done
        split_tile(smem, OFF_KHI, OFF_KLO,
                   (const float4*)(Kb + (size_t)kt * NTILE * D_DIM), wid, lane);
        __syncthreads();

        float acc[16][4];
        #pragma unroll
        for (int n = 0; n < 16; n++)
            #pragma unroll
            for (int r = 0; r < 4; r++) acc[n][r] = 0.f;

        #pragma unroll
        for (int ks = 0; ks < 8; ks++) {
            #pragma unroll
            for (int p = 0; p < 8; p++) {
                const uint32_t bo = b_off + (uint32_t)(p * 16 * RSTRIDE + ks * 32);
                uint32_t bh0, bh1, bh2, bh3, bl0, bl1, bl2, bl3;
                ldsm4(bh0, bh1, bh2, bh3, sb + OFF_KHI + bo);
                ldsm4(bl0, bl1, bl2, bl3, sb + OFF_KLO + bo);
                mma16816(acc[2 * p],     qhi[ks], bh0, bh1);
                mma16816(acc[2 * p + 1], qhi[ks], bh2, bh3);
                mma16816(acc[2 * p],     qlo[ks], bh0, bh1);
                mma16816(acc[2 * p + 1], qlo[ks], bh2, bh3);
                mma16816(acc[2 * p],     qhi[ks], bl0, bl1);
                mma16816(acc[2 * p + 1], qhi[ks], bl2, bl3);
            }
        }

        // Store scores: row0 = 16w + l/4, row1 = +8; cols 8*nt + 2*(l&3)
        {
            const int g = lane >> 2;
            const int r0 = 16 * wid + g;
            const int cb = 2 * (lane & 3);
            #pragma unroll
            for (int n = 0; n < 16; n++) {
                const int c = 8 * n + cb;
                scores[r0 * SSTRIDE + c]           = acc[n][0];
                scores[r0 * SSTRIDE + c + 1]       = acc[n][1];
                scores[(r0 + 8) * SSTRIDE + c]     = acc[n][2];
                scores[(r0 + 8) * SSTRIDE + c + 1] = acc[n][3];
            }
        }
        __syncthreads();

        // Selection: thread q scans row q (conflict-free: bank = q + j)
        if (tid < QPB) {
            const float* row = scores + tid * SSTRIDE;
            const int kbase = kt * NTILE;
            #pragma unroll 4
            for (int j = 0; j < NTILE; j++) {
                float s = row[j];
                if (s > minv) {
                    mytopv[minpos] = s;
                    mytopi[minpos] = kbase + j;
                    minv = mytopv[0]; minpos = 0;
                    #pragma unroll 1
                    for (int i = 1; i < KTOP; i++) {
                        float v = mytopv[i];
                        if (v < minv) { minv = v; minpos = i; }
                    }
                }
            }
        }
    }

    // ---- Softmax over selected 32 (threads 0..127) ----
    if (tid < QPB) {
        float m = -3.402823466e38f;
        #pragma unroll 1
        for (int i = 0; i < KTOP; i++) m = fmaxf(m, mytopv[i]);
        float ssum = 0.f;
        #pragma unroll 1
        for (int i = 0; i < KTOP; i++) { float e = __expf(mytopv[i] - m); ssum += e; mytopv[i] = e; }
        float inv = 1.0f / ssum;
        #pragma unroll 1
        for (int i = 0; i < KTOP; i++) mytopv[i] *= inv;
    }
    __syncthreads();

    // ---- V gather: warp w handles queries [16w,16w+16), lane = float4 dim chunk ----
    float* Ob = Og + ((size_t)bh * S_LEN + q0) * D_DIM;
    #pragma unroll 1
    for (int qi = 0; qi < 16; qi++) {
        const int tq = 16 * wid + qi;
        const float* tv = (const float*)(smem + OFF_TOPV) + tq * 33;
        const int*   ti = (const int*)(smem + OFF_TOPI) + tq * 33;
        float4 a = make_float4(0.f, 0.f, 0.f, 0.f);
        #pragma unroll 4
        for (int j = 0; j < KTOP; j++) {
            float p = tv[j];
            float4 v = __ldg((const float4*)(Vb + (size_t)ti[j] * D_DIM) + lane);
            a.x += p * v.x; a.y += p * v.y; a.z += p * v.z; a.w += p * v.w;
        }
        ((float4*)(Ob + (size_t)tq * D_DIM))[lane] = a;
    }
}

extern "C" void kernel_launch(void* const* d_in, const int* in_sizes, int n_in,
                              void* d_out, int out_size) {
    const float* Q = (const float*)d_in[0];
    const float* K = (const float*)d_in[1];
    const float* V = (const float*)d_in[2];
    float* O = (float*)d_out;
    const int BH = in_sizes[0] / (S_LEN * D_DIM);
    cudaFuncSetAttribute(topk_attn_hmma, cudaFuncAttributeMaxDynamicSharedMemorySize, SMEM_TOTAL);
    dim3 grid(S_LEN / QPB, BH);
    topk_attn_hmma<<<grid, NTHREADS, SMEM_TOTAL>>>(Q, K, V, O);
}

// round 4
// speedup vs baseline: 8.0344x; 7.0907x over previous
#include <cuda_runtime.h>
#include <cuda_bf16.h>
#include <cstdint>
#include <cfloat>

#define S_LEN 2048
#define D_DIM 128
#define QPB   128
#define NKT   16
#define KTOP  32
#define RSTRIDE 272        // bf16 tile row stride (17*16B): conflict-free ldmatrix

// 512 MB global scratch for the full score matrix [BH=32][2048][2048] fp32
__device__ float g_scores[(size_t)32 * S_LEN * S_LEN];

__device__ __forceinline__ uint32_t smem_u32(const void* p) {
    uint32_t a;
    asm("{ .reg .u64 t; cvta.to.shared.u64 t, %1; cvt.u32.u64 %0, t; }" : "=r"(a) : "l"(p));
    return a;
}

__device__ __forceinline__ void ldsm4(uint32_t& r0, uint32_t& r1, uint32_t& r2, uint32_t& r3,
                                      uint32_t addr) {
    asm volatile("ldmatrix.sync.aligned.m8n8.x4.shared.b16 {%0,%1,%2,%3}, [%4];"
                 : "=r"(r0), "=r"(r1), "=r"(r2), "=r"(r3) : "r"(addr));
}

__device__ __forceinline__ void mma16816(float* c, const uint32_t* a, uint32_t b0, uint32_t b1) {
    asm volatile(
        "mma.sync.aligned.m16n8k16.row.col.f32.bf16.bf16.f32 "
        "{%0,%1,%2,%3}, {%4,%5,%6,%7}, {%8,%9}, {%0,%1,%2,%3};"
        : "+f"(c[0]), "+f"(c[1]), "+f"(c[2]), "+f"(c[3])
        : "r"(a[0]), "r"(a[1]), "r"(a[2]), "r"(a[3]), "r"(b0), "r"(b1));
}

// Convert one float4 (4 dims of one row) to bf16 hi/lo pairs and store to smem tile.
__device__ __forceinline__ void cvt_store(char* smem, uint32_t hi_off, uint32_t lo_off,
                                          int row, int lane, float4 v) {
    __nv_bfloat16 h0 = __float2bfloat16(v.x), h1 = __float2bfloat16(v.y);
    __nv_bfloat16 h2 = __float2bfloat16(v.z), h3 = __float2bfloat16(v.w);
    __nv_bfloat16 l0 = __float2bfloat16(v.x - __bfloat162float(h0));
    __nv_bfloat16 l1 = __float2bfloat16(v.y - __bfloat162float(h1));
    __nv_bfloat16 l2 = __float2bfloat16(v.z - __bfloat162float(h2));
    __nv_bfloat16 l3 = __float2bfloat16(v.w - __bfloat162float(h3));
    uint2 hp, lp;
    hp.x = (uint32_t)__bfloat16_as_ushort(h0) | ((uint32_t)__bfloat16_as_ushort(h1) << 16);
    hp.y = (uint32_t)__bfloat16_as_ushort(h2) | ((uint32_t)__bfloat16_as_ushort(h3) << 16);
    lp.x = (uint32_t)__bfloat16_as_ushort(l0) | ((uint32_t)__bfloat16_as_ushort(l1) << 16);
    lp.y = (uint32_t)__bfloat16_as_ushort(l2) | ((uint32_t)__bfloat16_as_ushort(l3) << 16);
    *(uint2*)(smem + hi_off + row * RSTRIDE + lane * 8) = hp;
    *(uint2*)(smem + lo_off + row * RSTRIDE + lane * 8) = lp;
}

// ---------------- Kernel A: scores = Q K^T (bf16 3-term split), write to scratch ----------------
#define NT_A 512
#define AQHI 0
#define AQLO 34816
#define AKB(b) (69632 + (b) * 69632)          // K buffer b: hi at AKB, lo at AKB+34816
#define SMEM_A (69632 * 3)                    // 208896

__global__ __launch_bounds__(NT_A, 1)
void scores_kernel(const float* __restrict__ Qg, const float* __restrict__ Kg) {
    extern __shared__ char smem[];
    const uint32_t sb = smem_u32(smem);
    const int tid = threadIdx.x, wid = tid >> 5, lane = tid & 31;
    const int bh = blockIdx.y, q0 = blockIdx.x * QPB;
    const float* Kb = Kg + (size_t)bh * S_LEN * D_DIM;

    // Split Q (128x128) into AQHI/AQLO: 8 passes, row = p*16 + wid, col = lane.
    {
        const float4* src = (const float4*)(Qg + ((size_t)bh * S_LEN + q0) * D_DIM);
        #pragma unroll
        for (int p = 0; p < 8; p++) {
            const int row = p * 16 + wid;
            cvt_store(smem, AQHI, AQLO, row, lane, __ldg(src + (size_t)row * 32 + lane));
        }
    }
    // Split K tile 0 into buffer 0.
    {
        #pragma unroll
        for (int p = 0; p < 8; p++) {
            const int row = p * 16 + wid;
            cvt_store(smem, AKB(0), AKB(0) + 34816, row, lane,
                      __ldg((const float4*)Kb + (size_t)row * 32 + lane));
        }
    }
    __syncthreads();

    const int wr = wid & 7, wc = wid >> 3;     // M strip 16*wr, N half 64*wc
    const uint32_t a_off = (uint32_t)((16 * wr + (((lane >> 3) & 1) << 3) + (lane & 7)) * RSTRIDE
                                      + ((lane >> 4) << 4));
    const uint32_t b_off = (uint32_t)((64 * wc + (((lane >> 4) & 1) << 3) + (lane & 7)) * RSTRIDE
                                      + (((lane >> 3) & 1) << 4));
    const int r0 = q0 + 16 * wr + (lane >> 2);
    float* srow0 = g_scores + ((size_t)(bh * S_LEN + r0)) * S_LEN;

    for (int kt = 0; kt < NKT; kt++) {
        // Prefetch next K tile into registers (latency hidden behind MMAs).
        float4 pf[8];
        if (kt < NKT - 1) {
            const float4* src = (const float4*)(Kb + (size_t)(kt + 1) * 128 * D_DIM);
            #pragma unroll
            for (int p = 0; p < 8; p++) pf[p] = __ldg(src + (size_t)(p * 16 + wid) * 32 + lane);
        }

        const uint32_t khi = sb + AKB(kt & 1), klo = khi + 34816;
        float acc[8][4];
        #pragma unroll
        for (int n = 0; n < 8; n++)
            #pragma unroll
            for (int r = 0; r < 4; r++) acc[n][r] = 0.f;

        #pragma unroll
        for (int ks = 0; ks < 8; ks++) {
            uint32_t ah[4], al[4];
            ldsm4(ah[0], ah[1], ah[2], ah[3], sb + AQHI + a_off + ks * 32);
            ldsm4(al[0], al[1], al[2], al[3], sb + AQLO + a_off + ks * 32);
            #pragma unroll
            for (int p = 0; p < 4; p++) {
                const uint32_t bo = b_off + (uint32_t)(p * 16 * RSTRIDE + ks * 32);
                uint32_t b0, b1, b2, b3, c0, c1, c2, c3;
                ldsm4(b0, b1, b2, b3, khi + bo);
                ldsm4(c0, c1, c2, c3, klo + bo);
                mma16816(acc[2 * p],     ah, b0, b1);
                mma16816(acc[2 * p + 1], ah, b2, b3);
                mma16816(acc[2 * p],     al, b0, b1);
                mma16816(acc[2 * p + 1], al, b2, b3);
                mma16816(acc[2 * p],     ah, c0, c1);
                mma16816(acc[2 * p + 1], ah, c2, c3);
            }
        }

        // Store scores: 16 x STG.64, 32B-contiguous groups per 4 lanes.
        const int cb = kt * 128 + 64 * wc + 2 * (lane & 3);
        #pragma unroll
        for (int n = 0; n < 8; n++) {
            *(float2*)(srow0 + cb + 8 * n) = make_float2(acc[n][0], acc[n][1]);
            *(float2*)(srow0 + (size_t)8 * S_LEN + cb + 8 * n) = make_float2(acc[n][2], acc[n][3]);
        }

        if (kt < NKT - 1) {
            const uint32_t dst = AKB((kt + 1) & 1);
            #pragma unroll
            for (int p = 0; p < 8; p++)
                cvt_store(smem, dst, dst + 34816, p * 16 + wid, lane, pf[p]);
        }
        __syncthreads();
    }
}

// ---------------- Kernel B: warp-per-query top-32 + softmax + V gather ----------------
#define NT_B 256
#define BWARPS 8
#define LSTRIDE 68                      // floats per lane buffer (64 used, 272B aligned)
#define SMEM_B (BWARPS * 32 * LSTRIDE * 4)   // 69632

__global__ __launch_bounds__(NT_B, 2)
void select_kernel(const float* __restrict__ Vg, float* __restrict__ Og) {
    extern __shared__ char smem[];
    const int tid = threadIdx.x, wid = tid >> 5, lane = tid & 31;
    const int q = blockIdx.x * BWARPS + wid;        // global query (bh*2048 + s)
    const int bh = q >> 11;
    float* buf = (float*)(smem + (size_t)wid * 32 * LSTRIDE * 4) + lane * LSTRIDE;
    const float* srow = g_scores + (size_t)q * S_LEN;

    // Load 64 scores per lane; cache per-group (16 values) max.
    float gmax[4];
    int   gj[4];
    #pragma unroll
    for (int g = 0; g < 4; g++) { gmax[g] = -FLT_MAX; gj[g] = g << 4; }
    #pragma unroll
    for (int i = 0; i < 16; i++) {
        float4 v = __ldg((const float4*)srow + i * 32 + lane);
        ((float4*)buf)[i] = v;
        const int g = i >> 2;
        if (v.x > gmax[g]) { gmax[g] = v.x; gj[g] = 4 * i + 0; }
        if (v.y > gmax[g]) { gmax[g] = v.y; gj[g] = 4 * i + 1; }
        if (v.z > gmax[g]) { gmax[g] = v.z; gj[g] = 4 * i + 2; }
        if (v.w > gmax[g]) { gmax[g] = v.w; gj[g] = 4 * i + 3; }
    }

    // 32 rounds of warp argmax; lane r keeps round r's (val, key) in registers.
    float    myval = 0.f;
    unsigned mykey = 0;
    for (int r = 0; r < KTOP; r++) {
        float bv = gmax[0]; int bj = gj[0];
        if (gmax[1] > bv) { bv = gmax[1]; bj = gj[1]; }
        if (gmax[2] > bv) { bv = gmax[2]; bj = gj[2]; }
        if (gmax[3] > bv) { bv = gmax[3]; bj = gj[3]; }
        // key = actual column index = 128*i + 4*lane + c, with i = bj>>2, c = bj&3
        unsigned key = ((unsigned)(bj >> 2) << 7) | ((unsigned)lane << 2) | (unsigned)(bj & 3);
        #pragma unroll
        for (int o = 16; o; o >>= 1) {
            float    v2 = __shfl_xor_sync(0xffffffffu, bv, o);
            unsigned k2 = __shfl_xor_sync(0xffffffffu, key, o);
            if (v2 > bv || (v2 == bv && k2 < key)) { bv = v2; key = k2; }
        }
        // Winner lane removes the element and rescans its dirty group.
        if (lane == (int)((key >> 2) & 31)) {
            const int j = (int)(((key >> 7) << 2) | (key & 3));
            buf[j] = -FLT_MAX;
            const int g = j >> 4;
            float m = -FLT_MAX; int mj = g << 4;
            #pragma unroll
            for (int jj = 0; jj < 16; jj++) {
                float v = buf[(g << 4) + jj];
                if (v > m) { m = v; mj = (g << 4) + jj; }
            }
            gmax[g] = m; gj[g] = mj;
        }
        if (lane == r) { myval = bv; mykey = key; }
    }

    // Softmax over the 32 selected (lane j holds value j; round 0 = max).
    const float mx = __shfl_sync(0xffffffffu, myval, 0);
    float e = __expf(myval - mx);
    float s = e;
    #pragma unroll
    for (int o = 16; o; o >>= 1) s += __shfl_xor_sync(0xffffffffu, s, o);
    const float p = e / s;

    // V gather: warp reads each selected row once; lane owns dims [4l,4l+4).
    const float* Vb = Vg + (size_t)bh * S_LEN * D_DIM;
    float4 a = make_float4(0.f, 0.f, 0.f, 0.f);
    #pragma unroll 4
    for (int j = 0; j < KTOP; j++) {
        const float    pj = __shfl_sync(0xffffffffu, p, j);
        const unsigned kj = __shfl_sync(0xffffffffu, mykey, j);
        float4 v = __ldg((const float4*)(Vb + (size_t)kj * D_DIM) + lane);
        a.x += pj * v.x; a.y += pj * v.y; a.z += pj * v.z; a.w += pj * v.w;
    }
    ((float4*)(Og + (size_t)q * D_DIM))[lane] = a;
}

extern "C" void kernel_launch(void* const* d_in, const int* in_sizes, int n_in,
                              void* d_out, int out_size) {
    const float* Q = (const float*)d_in[0];
    const float* K = (const float*)d_in[1];
    const float* V = (const float*)d_in[2];
    float* O = (float*)d_out;
    const int BH = in_sizes[0] / (S_LEN * D_DIM);   // 32

    cudaFuncSetAttribute(scores_kernel, cudaFuncAttributeMaxDynamicSharedMemorySize, SMEM_A);
    cudaFuncSetAttribute(select_kernel, cudaFuncAttributeMaxDynamicSharedMemorySize, SMEM_B);

    dim3 gridA(S_LEN / QPB, BH);
    scores_kernel<<<gridA, NT_A, SMEM_A>>>(Q, K);

    const int nq = BH * S_LEN;
    select_kernel<<<nq / BWARPS, NT_B, SMEM_B>>>(V, O);
}

// round 5
// speedup vs baseline: 12.2066x; 1.5193x over previous
#include <cuda_runtime.h>
#include <cuda_bf16.h>
#include <cstdint>
#include <cfloat>

#define S_LEN 2048
#define D_DIM 128
#define QPB   128
#define NKT   16
#define KTOP  32
#define RSTRIDE 272        // bf16 tile row stride (17*16B): conflict-free ldmatrix

// 512 MB global scratch for the full score matrix [BH=32][2048][2048] fp32
__device__ float g_scores[(size_t)32 * S_LEN * S_LEN];

__device__ __forceinline__ uint32_t smem_u32(const void* p) {
    uint32_t a;
    asm("{ .reg .u64 t; cvta.to.shared.u64 t, %1; cvt.u32.u64 %0, t; }" : "=r"(a) : "l"(p));
    return a;
}

__device__ __forceinline__ void ldsm4(uint32_t& r0, uint32_t& r1, uint32_t& r2, uint32_t& r3,
                                      uint32_t addr) {
    asm volatile("ldmatrix.sync.aligned.m8n8.x4.shared.b16 {%0,%1,%2,%3}, [%4];"
                 : "=r"(r0), "=r"(r1), "=r"(r2), "=r"(r3) : "r"(addr));
}

__device__ __forceinline__ void mma16816(float* c, const uint32_t* a, uint32_t b0, uint32_t b1) {
    asm volatile(
        "mma.sync.aligned.m16n8k16.row.col.f32.bf16.bf16.f32 "
        "{%0,%1,%2,%3}, {%4,%5,%6,%7}, {%8,%9}, {%0,%1,%2,%3};"
        : "+f"(c[0]), "+f"(c[1]), "+f"(c[2]), "+f"(c[3])
        : "r"(a[0]), "r"(a[1]), "r"(a[2]), "r"(a[3]), "r"(b0), "r"(b1));
}

// Convert one float4 (4 dims of one row) to bf16 hi/lo pairs and store to smem tile.
__device__ __forceinline__ void cvt_store(char* smem, uint32_t hi_off, uint32_t lo_off,
                                          int row, int lane, float4 v) {
    __nv_bfloat16 h0 = __float2bfloat16(v.x), h1 = __float2bfloat16(v.y);
    __nv_bfloat16 h2 = __float2bfloat16(v.z), h3 = __float2bfloat16(v.w);
    __nv_bfloat16 l0 = __float2bfloat16(v.x - __bfloat162float(h0));
    __nv_bfloat16 l1 = __float2bfloat16(v.y - __bfloat162float(h1));
    __nv_bfloat16 l2 = __float2bfloat16(v.z - __bfloat162float(h2));
    __nv_bfloat16 l3 = __float2bfloat16(v.w - __bfloat162float(h3));
    uint2 hp, lp;
    hp.x = (uint32_t)__bfloat16_as_ushort(h0) | ((uint32_t)__bfloat16_as_ushort(h1) << 16);
    hp.y = (uint32_t)__bfloat16_as_ushort(h2) | ((uint32_t)__bfloat16_as_ushort(h3) << 16);
    lp.x = (uint32_t)__bfloat16_as_ushort(l0) | ((uint32_t)__bfloat16_as_ushort(l1) << 16);
    lp.y = (uint32_t)__bfloat16_as_ushort(l2) | ((uint32_t)__bfloat16_as_ushort(l3) << 16);
    *(uint2*)(smem + hi_off + row * RSTRIDE + lane * 8) = hp;
    *(uint2*)(smem + lo_off + row * RSTRIDE + lane * 8) = lp;
}

// ---------------- Kernel A: scores = Q K^T (bf16 3-term split), write to scratch ----------------
#define NT_A 512
#define AQHI 0
#define AQLO 34816
#define AKB(b) (69632 + (b) * 69632)          // K buffer b: hi at AKB, lo at AKB+34816
#define SMEM_A (69632 * 3)                    // 208896

__global__ __launch_bounds__(NT_A, 1)
void scores_kernel(const float* __restrict__ Qg, const float* __restrict__ Kg) {
    extern __shared__ char smem[];
    const uint32_t sb = smem_u32(smem);
    const int tid = threadIdx.x, wid = tid >> 5, lane = tid & 31;
    const int bh = blockIdx.y, q0 = blockIdx.x * QPB;
    const float* Kb = Kg + (size_t)bh * S_LEN * D_DIM;

    {
        const float4* src = (const float4*)(Qg + ((size_t)bh * S_LEN + q0) * D_DIM);
        #pragma unroll
        for (int p = 0; p < 8; p++) {
            const int row = p * 16 + wid;
            cvt_store(smem, AQHI, AQLO, row, lane, __ldg(src + (size_t)row * 32 + lane));
        }
    }
    {
        #pragma unroll
        for (int p = 0; p < 8; p++) {
            const int row = p * 16 + wid;
            cvt_store(smem, AKB(0), AKB(0) + 34816, row, lane,
                      __ldg((const float4*)Kb + (size_t)row * 32 + lane));
        }
    }
    __syncthreads();

    const int wr = wid & 7, wc = wid >> 3;     // M strip 16*wr, N half 64*wc
    const uint32_t a_off = (uint32_t)((16 * wr + (((lane >> 3) & 1) << 3) + (lane & 7)) * RSTRIDE
                                      + ((lane >> 4) << 4));
    const uint32_t b_off = (uint32_t)((64 * wc + (((lane >> 4) & 1) << 3) + (lane & 7)) * RSTRIDE
                                      + (((lane >> 3) & 1) << 4));
    const int r0 = q0 + 16 * wr + (lane >> 2);
    float* srow0 = g_scores + ((size_t)(bh * S_LEN + r0)) * S_LEN;

    for (int kt = 0; kt < NKT; kt++) {
        float4 pf[8];
        if (kt < NKT - 1) {
            const float4* src = (const float4*)(Kb + (size_t)(kt + 1) * 128 * D_DIM);
            #pragma unroll
            for (int p = 0; p < 8; p++) pf[p] = __ldg(src + (size_t)(p * 16 + wid) * 32 + lane);
        }

        const uint32_t khi = sb + AKB(kt & 1), klo = khi + 34816;
        float acc[8][4];
        #pragma unroll
        for (int n = 0; n < 8; n++)
            #pragma unroll
            for (int r = 0; r < 4; r++) acc[n][r] = 0.f;

        #pragma unroll
        for (int ks = 0; ks < 8; ks++) {
            uint32_t ah[4], al[4];
            ldsm4(ah[0], ah[1], ah[2], ah[3], sb + AQHI + a_off + ks * 32);
            ldsm4(al[0], al[1], al[2], al[3], sb + AQLO + a_off + ks * 32);
            #pragma unroll
            for (int p = 0; p < 4; p++) {
                const uint32_t bo = b_off + (uint32_t)(p * 16 * RSTRIDE + ks * 32);
                uint32_t b0, b1, b2, b3, c0, c1, c2, c3;
                ldsm4(b0, b1, b2, b3, khi + bo);
                ldsm4(c0, c1, c2, c3, klo + bo);
                mma16816(acc[2 * p],     ah, b0, b1);
                mma16816(acc[2 * p + 1], ah, b2, b3);
                mma16816(acc[2 * p],     al, b0, b1);
                mma16816(acc[2 * p + 1], al, b2, b3);
                mma16816(acc[2 * p],     ah, c0, c1);
                mma16816(acc[2 * p + 1], ah, c2, c3);
            }
        }

        const int cb = kt * 128 + 64 * wc + 2 * (lane & 3);
        #pragma unroll
        for (int n = 0; n < 8; n++) {
            *(float2*)(srow0 + cb + 8 * n) = make_float2(acc[n][0], acc[n][1]);
            *(float2*)(srow0 + (size_t)8 * S_LEN + cb + 8 * n) = make_float2(acc[n][2], acc[n][3]);
        }

        if (kt < NKT - 1) {
            const uint32_t dst = AKB((kt + 1) & 1);
            #pragma unroll
            for (int p = 0; p < 8; p++)
                cvt_store(smem, dst, dst + 34816, p * 16 + wid, lane, pf[p]);
        }
        __syncthreads();
    }
}

// ---------------- Kernel B: warp-per-query top-32 via redux tournament ----------------
#define NT_B 256
#define BWARPS 8
#define SMEM_B (BWARPS * 32 * 64 * 4)   // 65536: 64 floats per lane, chunk-swizzled

// monotonic float<->u32 order-preserving map
__device__ __forceinline__ unsigned fmono(float f) {
    unsigned u = __float_as_uint(f);
    return u ^ ((unsigned)((int)u >> 31) | 0x80000000u);
}
__device__ __forceinline__ float funmono(unsigned m) {
    return __uint_as_float(m ^ ((unsigned)((int)(~m) >> 31) | 0x80000000u));
}

__global__ __launch_bounds__(NT_B, 3)
void select_kernel(const float* __restrict__ Vg, float* __restrict__ Og) {
    extern __shared__ float sbuf[];
    const int tid = threadIdx.x, wid = tid >> 5, lane = tid & 31;
    const int q = blockIdx.x * BWARPS + wid;       // global query = bh*2048 + s
    const int bh = q >> 11;
    float* buf = sbuf + (size_t)wid * 2048;        // warp region: 32 lanes x 64 floats
    const float* srow = g_scores + (size_t)q * S_LEN;
    const unsigned FULL = 0xffffffffu;
    const int lsw = lane & 15;

    // Load 64 scores/lane (cols 128i + 4*lane + c); XOR-swizzled chunk store
    // (bank-conflict-free STS.128); track lane max (cand) branchlessly.
    float bv = -FLT_MAX; int bj = 0;
    #pragma unroll
    for (int i = 0; i < 16; i++) {
        float4 v = __ldg((const float4*)srow + i * 32 + lane);
        ((float4*)buf)[lane * 16 + (i ^ lsw)] = v;
        if (v.x > bv) { bv = v.x; bj = 4 * i; }
        if (v.y > bv) { bv = v.y; bj = 4 * i + 1; }
        if (v.z > bv) { bv = v.z; bj = 4 * i + 2; }
        if (v.w > bv) { bv = v.w; bj = 4 * i + 3; }
    }
    __syncwarp();

    // 32 tournament rounds. Invariant: each lane's (bv,bj) = max of its un-taken elems.
    float    selval = 0.f;
    unsigned selkey = 0;
    #pragma unroll 1
    for (int r = 0; r < KTOP; r++) {
        const unsigned mym = fmono(bv);
        const unsigned wm  = __reduce_max_sync(FULL, mym);
        const unsigned bal = __ballot_sync(FULL, mym == wm);
        const int wl = __ffs(bal) - 1;
        const unsigned mykey = ((unsigned)(bj >> 2) << 7) | ((unsigned)lane << 2) | (unsigned)(bj & 3);
        const unsigned wkey = __shfl_sync(FULL, mykey, wl);
        if (lane == r) { selval = funmono(wm); selkey = wkey; }

        // winner marks its taken element
        if (lane == wl)
            buf[lane * 64 + (((bj >> 2) ^ lsw) << 2) + (bj & 3)] = -FLT_MAX;
        __syncwarp();

        // cooperative refill: all lanes scan winner's 64-elem buffer (2 each)
        const int wsw = wl & 15;
        const float2 vv = *(const float2*)(buf + wl * 64 + (((lane >> 1) ^ wsw) << 2) + ((lane & 1) << 1));
        float rv; int rj;
        if (vv.x >= vv.y) { rv = vv.x; rj = 2 * lane; } else { rv = vv.y; rj = 2 * lane + 1; }
        const unsigned rm = fmono(rv);
        const unsigned rw = __reduce_max_sync(FULL, rm);
        const unsigned rb = __ballot_sync(FULL, rm == rw);
        const int rjw = __shfl_sync(FULL, rj, __ffs(rb) - 1);
        if (lane == wl) { bv = funmono(rw); bj = rjw; }
        __syncwarp();
    }

    // Softmax over the 32 selected (lane r holds round r; round 0 = max).
    const float mx = __shfl_sync(FULL, selval, 0);
    const float e = __expf(selval - mx);
    float s = e;
    #pragma unroll
    for (int o = 16; o; o >>= 1) s += __shfl_xor_sync(FULL, s, o);
    const float p = e / s;

    // V gather: warp reads each selected row once; lane owns dims [4l,4l+4).
    const float* Vb = Vg + (size_t)bh * S_LEN * D_DIM;
    float4 a = make_float4(0.f, 0.f, 0.f, 0.f);
    #pragma unroll 4
    for (int j = 0; j < KTOP; j++) {
        const float    pj = __shfl_sync(FULL, p, j);
        const unsigned kj = __shfl_sync(FULL, selkey, j);
        float4 v = __ldg((const float4*)(Vb + (size_t)kj * D_DIM) + lane);
        a.x += pj * v.x; a.y += pj * v.y; a.z += pj * v.z; a.w += pj * v.w;
    }
    ((float4*)(Og + (size_t)q * D_DIM))[lane] = a;
}

extern "C" void kernel_launch(void* const* d_in, const int* in_sizes, int n_in,
                              void* d_out, int out_size) {
    const float* Q = (const float*)d_in[0];
    const float* K = (const float*)d_in[1];
    const float* V = (const float*)d_in[2];
    float* O = (float*)d_out;
    const int BH = in_sizes[0] / (S_LEN * D_DIM);   // 32

    cudaFuncSetAttribute(scores_kernel, cudaFuncAttributeMaxDynamicSharedMemorySize, SMEM_A);
    cudaFuncSetAttribute(select_kernel, cudaFuncAttributeMaxDynamicSharedMemorySize, SMEM_B);

    dim3 gridA(S_LEN / QPB, BH);
    scores_kernel<<<gridA, NT_A, SMEM_A>>>(Q, K);

    const int nq = BH * S_LEN;
    select_kernel<<<nq / BWARPS, NT_B, SMEM_B>>>(V, O);
}